// round 14
// baseline (speedup 1.0000x reference)
#include <cuda_runtime.h>
#include <cuda_bf16.h>
#include <cstdint>

// CALayer SE, single-pass persistent kernel, cp.async double-buffered.
// 1024 co-resident blocks (LB(256,8): smem 17.2KB -> 8 blocks/SM, 1184 slots).
// Each block owns a 16KB quarter-plane chunk per batch. Round b:
//   sum chunk b from smem (fetched last round) -> publish counter(b)
//   issue cp.async fetch of chunk b+1 (flies across the whole serial tail)
//   gate(b-1) [1-round slack], means + tiny MLP
//   scale chunk b-1 via ld.cg (L2 hit), st.cs out
//   wait_group 0 (fetch b+1 done), sync
// DRAM reads issue continuously via cp.async; traffic = 537MB.

#define BATCH 16
#define CHAN 256
#define CR 16
#define HW 16384               // floats per plane
#define PLANE_F4 (HW/4)        // 4096
#define QF4 (PLANE_F4/4)       // 1024 float4 per 16KB chunk
#define NBLK 1024
#define TPB 256

__device__ float g_part[BATCH * CHAN * 4];
__device__ int   g_cnt[BATCH];
__device__ int   g_done[BATCH];

__device__ __forceinline__ void stcs4(float4* p, float4 v) {
    asm volatile("st.global.cs.v4.f32 [%0], {%1,%2,%3,%4};"
                 :: "l"(p), "f"(v.x), "f"(v.y), "f"(v.z), "f"(v.w) : "memory");
}
__device__ __forceinline__ float4 ldcg4(const float4* p) {
    float4 v;
    asm volatile("ld.global.cg.v4.f32 {%0,%1,%2,%3}, [%4];"
                 : "=f"(v.x), "=f"(v.y), "=f"(v.z), "=f"(v.w) : "l"(p));
    return v;
}
__device__ __forceinline__ void cpasync16(unsigned int dst, const void* src) {
    asm volatile("cp.async.cg.shared.global [%0], [%1], 16;"
                 :: "r"(dst), "l"(src) : "memory");
}
__device__ __forceinline__ void cpasync_commit() {
    asm volatile("cp.async.commit_group;" ::: "memory");
}
__device__ __forceinline__ void cpasync_wait0() {
    asm volatile("cp.async.wait_group 0;" ::: "memory");
}
__device__ __forceinline__ unsigned int smem_u32(const void* p) {
    unsigned int a;
    asm("{ .reg .u64 t; cvta.to.shared.u64 t, %1; cvt.u32.u64 %0, t; }"
        : "=r"(a) : "l"(p));
    return a;
}

__global__ __launch_bounds__(TPB, 8) void fused_se_kernel(
    const float* __restrict__ x, float* __restrict__ out,
    const float* __restrict__ w1, const float* __restrict__ b1,
    const float* __restrict__ w2, const float* __restrict__ b2)
{
    __shared__ float4 ring[QF4];     // 16KB fetch buffer
    __shared__ float sred[8];
    __shared__ float smean[CHAN];
    __shared__ float shid[CR];
    __shared__ float sscale;

    const int chan    = blockIdx.x >> 2;
    const int quarter = blockIdx.x & 3;
    const int tid  = threadIdx.x;
    const int lane = tid & 31;
    const int wid  = tid >> 5;
    const size_t qoff = (size_t)quarter * QF4;

    const float4* __restrict__ x4 = reinterpret_cast<const float4*>(x);
    float4* __restrict__ o4 = reinterpret_cast<float4*>(out);
    const unsigned int rb = smem_u32(ring);

    auto chunk = [&](int b) {
        return x4 + (size_t)((b << 8) | chan) * PLANE_F4 + qoff;
    };
    auto ochunk = [&](int b) {
        return o4 + (size_t)((b << 8) | chan) * PLANE_F4 + qoff;
    };

    auto fetch = [&](int b) {   // async: chunk b -> ring (fills L2 on the way)
        const float4* src = chunk(b);
        #pragma unroll
        for (int i = 0; i < 4; i++)
            cpasync16(rb + (unsigned)(tid + i * TPB) * 16u, src + tid + i * TPB);
        cpasync_commit();
    };

    auto gate_mlp = [&](int b) {
        if (tid == 0) {
            while (atomicAdd(&g_cnt[b], 0) < NBLK) __nanosleep(64);
            __threadfence();
            if (atomicAdd(&g_done[b], 1) == NBLK - 1) {   // last one resets
                atomicExch(&g_cnt[b], 0);
                atomicExch(&g_done[b], 0);
            }
        }
        __syncthreads();
        {
            const int q = ((b << 8) + tid) * 4;
            smean[tid] = (__ldcg(&g_part[q]) + __ldcg(&g_part[q + 1]) +
                          __ldcg(&g_part[q + 2]) + __ldcg(&g_part[q + 3])) * (1.0f / HW);
        }
        __syncthreads();
        #pragma unroll
        for (int k = 0; k < 2; k++) {
            const int r = wid * 2 + k;
            float acc = 0.f;
            #pragma unroll
            for (int c = lane; c < CHAN; c += 32)
                acc += __ldg(&w1[r * CHAN + c]) * smean[c];
            #pragma unroll
            for (int o = 16; o; o >>= 1) acc += __shfl_xor_sync(0xFFFFFFFF, acc, o);
            if (lane == 0) shid[r] = fmaxf(acc + __ldg(&b1[r]), 0.f);
        }
        __syncthreads();
        if (tid == 0) {
            float acc = __ldg(&b2[chan]);
            #pragma unroll
            for (int r = 0; r < CR; r++)
                acc += __ldg(&w2[chan * CR + r]) * shid[r];
            sscale = 1.0f / (1.0f + __expf(-acc));
        }
        __syncthreads();
    };

    auto scale_l2 = [&](int b) {    // re-read chunk b from L2, scale, stream out
        const float sc = sscale;
        const float4* __restrict__ xs = chunk(b);
        float4* __restrict__ os = ochunk(b);
        #pragma unroll
        for (int i = 0; i < 4; i++) {
            const int idx = tid + i * TPB;
            float4 w = ldcg4(&xs[idx]);
            w.x *= sc; w.y *= sc; w.z *= sc; w.w *= sc;
            stcs4(&os[idx], w);
        }
    };

    // ---------- prologue: fetch chunk 0 ----------
    fetch(0);
    cpasync_wait0();
    __syncthreads();

    // ---------- main loop ----------
    for (int b = 0; b < BATCH; b++) {
        // sum chunk b from smem
        float acc = 0.f;
        #pragma unroll
        for (int i = 0; i < 4; i++) {
            float4 v = ring[tid + i * TPB];
            acc += (v.x + v.y) + (v.z + v.w);
        }
        #pragma unroll
        for (int o = 16; o; o >>= 1) acc += __shfl_xor_sync(0xFFFFFFFF, acc, o);
        if (lane == 0) sred[wid] = acc;
        __syncthreads();                       // all reads of ring done

        if (b + 1 < BATCH) fetch(b + 1);       // flies across the serial tail

        if (tid == 0) {
            float t = 0.f;
            #pragma unroll
            for (int w = 0; w < 8; w++) t += sred[w];
            g_part[((((b << 8) | chan)) << 2) + quarter] = t;
            __threadfence();
            atomicAdd(&g_cnt[b], 1);
        }

        if (b >= 1) {                          // consume previous batch
            gate_mlp(b - 1);
            scale_l2(b - 1);
        }

        if (b + 1 < BATCH) {
            cpasync_wait0();                   // fetch had the whole tail to land
            __syncthreads();
        }
    }

    // ---------- tail ----------
    gate_mlp(BATCH - 1);
    scale_l2(BATCH - 1);
}

extern "C" void kernel_launch(void* const* d_in, const int* in_sizes, int n_in,
                              void* d_out, int out_size) {
    const float* x  = (const float*)d_in[0];
    const float* w1 = (const float*)d_in[1];
    const float* b1 = (const float*)d_in[2];
    const float* w2 = (const float*)d_in[3];
    const float* b2 = (const float*)d_in[4];
    float* out = (float*)d_out;

    fused_se_kernel<<<NBLK, TPB>>>(x, out, w1, b1, w2, b2);
}